// round 17
// baseline (speedup 1.0000x reference)
#include <cuda_runtime.h>
#include <cstdint>

// Problem shapes (fixed by the reference)
#define B_  8
#define T_  512
#define H_  8
#define D_  128
#define S_  8192

#define N_ELEM   (B_ * S_ * H_ * D_)     // 67,108,864 floats per cache tensor
#define N4_      (N_ELEM / 4)            // float4 per tensor
#define ROW4_    (H_ * D_ / 4)           // 256 float4 per (b,p) row

// ---------------------------------------------------------------------------
// Single fused kernel (joint K+V, register-dieted).
// One 256-thread block = 4 consecutive (b,p) rows (same b; S % 4 == 0).
//
// Phase 1 (L2-only, ~free): scan positions[b, 0..511] (2 KB, L2-resident)
// as 256 x int2; values in this block's 4-row window publish t+1 into a
// 4-entry smem table (0 = row not updated).
//
// Phase 2: 64 threads per row; each thread handles 4 float4 of K and 4 of V
// at stride 64 (warp-level 512B contiguous transactions, MLP=8/thread).
// KEY: f4 = d16 + 64j  =>  f4 & 31 = d16 & 31 for every j, so ONE cos/sin
// float2 pair per thread covers all 4 K-float4 (R15 loaded 4 redundant
// pairs and burned 24 regs). V is stored immediately after its loads to
// shorten live ranges. Target: <=42 regs -> 6 blocks/SM (62.5% occ).
// Every output element written exactly once; replaced cache rows never read.
// ---------------------------------------------------------------------------
__global__ void __launch_bounds__(256, 6) fused_write_kernel(
    const float4* __restrict__ k_new,      // (B,T,H,D) as float4
    const float4* __restrict__ v_new,
    const float2* __restrict__ cos_t,      // (S, D/2) as float2 pairs
    const float2* __restrict__ sin_t,
    const float4* __restrict__ cache_k,    // (B,S,H,D) as float4
    const float4* __restrict__ cache_v,
    const int*    __restrict__ positions,  // (B,T) int32
    float4* __restrict__ out)              // (2,B,S,H,D)
{
    __shared__ int t1s[4];                 // t+1 per row in window, 0 = empty

    const int tid    = threadIdx.x;
    const int row0   = blockIdx.x << 2;    // first of 4 rows: b*S + p_base
    const int b      = row0 >> 13;         // / S_
    const int p_base = row0 & (S_ - 1);

    // ---- Phase 1: build 4-entry inverse table from positions[b,:] ----
    if (tid < 4) t1s[tid] = 0;
    __syncthreads();
    {
        const int2 pv = __ldg(&((const int2*)(positions + b * T_))[tid]);
        const int d0 = pv.x - p_base;
        const int d1 = pv.y - p_base;
        if ((unsigned)d0 < 4u) t1s[d0] = 2 * tid + 1;   // t+1, t = 2*tid
        if ((unsigned)d1 < 4u) t1s[d1] = 2 * tid + 2;   // t+1, t = 2*tid+1
    }
    __syncthreads();

    // ---- Phase 2: streaming write of 4 rows ----
    const int rl  = tid >> 6;              // row within group: 0..3
    const int d16 = tid & 63;              // lane within row
    const int row = row0 + rl;
    const int p   = p_base + rl;

    const int t1 = t1s[rl];                // uniform per 64-thread row group

    const long long dstK = (long long)row * ROW4_;
    const long long dstV = dstK + N4_;

    if (t1 > 0) {
        const int t = t1 - 1;
        const long long src = ((long long)b * T_ + t) * ROW4_;

        // One cos/sin pair serves all 4 j (f4 & 31 == d16 & 31).
        const long long cs = (long long)p * (D_ / 4) + (d16 & 31);
        const float2 c = __ldg(&cos_t[cs]);
        const float2 s = __ldg(&sin_t[cs]);

        float4 k[4], v[4];
#pragma unroll
        for (int j = 0; j < 4; j++) {
            const int f4 = d16 + (j << 6);
            v[j] = __ldcs(&v_new[src + f4]);
            k[j] = __ldcs(&k_new[src + f4]);
        }
        // Store V first to retire v[] registers early.
#pragma unroll
        for (int j = 0; j < 4; j++)
            __stcs(&out[dstV + d16 + (j << 6)], v[j]);
#pragma unroll
        for (int j = 0; j < 4; j++) {
            const int f4 = d16 + (j << 6);
            float4 r;
            r.x = k[j].x * c.x - k[j].y * s.x;
            r.y = k[j].x * s.x + k[j].y * c.x;
            r.z = k[j].z * c.y - k[j].w * s.y;
            r.w = k[j].z * s.y + k[j].w * c.y;
            __stcs(&out[dstK + f4], r);
        }
    } else {
        float4 k[4], v[4];
#pragma unroll
        for (int j = 0; j < 4; j++) {
            const int f4 = d16 + (j << 6);
            k[j] = __ldcs(&cache_k[dstK + f4]);
            v[j] = __ldcs(&cache_v[dstK + f4]);
        }
#pragma unroll
        for (int j = 0; j < 4; j++) {
            const int f4 = d16 + (j << 6);
            __stcs(&out[dstK + f4], k[j]);
            __stcs(&out[dstV + f4], v[j]);
        }
    }
}

// ---------------------------------------------------------------------------
// Single launch. Inputs (metadata order):
//   0: k_new (B,T,H,D) f32      1: v_new (B,T,H,D) f32
//   2: cos (S,D/2) f32          3: sin (S,D/2) f32
//   4: cache_k (B,S,H,D) f32    5: cache_v (B,S,H,D) f32
//   6: positions (B,T) int32
// ---------------------------------------------------------------------------
extern "C" void kernel_launch(void* const* d_in, const int* in_sizes, int n_in,
                              void* d_out, int out_size)
{
    const float4* k_new   = (const float4*)d_in[0];
    const float4* v_new   = (const float4*)d_in[1];
    const float2* cos_t   = (const float2*)d_in[2];
    const float2* sin_t   = (const float2*)d_in[3];
    const float4* cache_k = (const float4*)d_in[4];
    const float4* cache_v = (const float4*)d_in[5];
    const int*    pos     = (const int*)d_in[6];
    float4* out = (float4*)d_out;

    fused_write_kernel<<<(B_ * S_) / 4, 256>>>(k_new, v_new, cos_t, sin_t,
                                               cache_k, cache_v, pos, out);
}